// round 1
// baseline (speedup 1.0000x reference)
#include <cuda_runtime.h>
#include <cuda_bf16.h>
#include <cstddef>

// Problem dims (fixed by the reference setup_inputs)
#define BB 32
#define SS 2048
#define DD 1024
#define D4 (DD / 4)          // 256 float4 per row
#define ROWS_PER_WARP 16
#define WARPS 8
#define NCHUNK (SS / (ROWS_PER_WARP * WARPS))   // 16
#define PP (NCHUNK * WARPS)  // 128 partials per batch

// Scratch (allocation-free rule: __device__ globals)
__device__ float  g_logits[BB * SS];            // 256 KB, masked logits
__device__ float  g_m[BB * PP];
__device__ float  g_l[BB * PP];
__device__ float4 g_wc[(size_t)BB * PP * D4];   // 16 MB partial weighted sums

// ---------------------------------------------------------------------------
// Pass 1: single streaming pass over context with online softmax.
// grid = (NCHUNK, BB), block = 256 (8 warps). Each warp: 16 consecutive rows.
// ---------------------------------------------------------------------------
__global__ __launch_bounds__(256)
void attn_pass1(const float* __restrict__ h,
                const float* __restrict__ ctx,
                const int* __restrict__ mask)
{
    const int b     = blockIdx.y;
    const int chunk = blockIdx.x;
    const int warp  = threadIdx.x >> 5;
    const int lane  = threadIdx.x & 31;
    const int p     = chunk * WARPS + warp;     // partial index in [0,128)
    const int s0    = p * ROWS_PER_WARP;        // first row of this warp

    // h row -> registers (same slots reused for every context row)
    const float4* h4 = reinterpret_cast<const float4*>(h) + b * D4;
    float4 hr[8];
#pragma unroll
    for (int j = 0; j < 8; j++) hr[j] = h4[lane + 32 * j];

    float m = -3.0e38f;   // running max (finite sentinel)
    float l = 0.0f;       // running sum of exp
    float4 wc[8];
#pragma unroll
    for (int j = 0; j < 8; j++) wc[j] = make_float4(0.f, 0.f, 0.f, 0.f);

    const float4* cbase = reinterpret_cast<const float4*>(ctx)
                          + ((size_t)b * SS + s0) * D4;
    const int* mrow = mask + b * SS + s0;

    for (int r = 0; r < ROWS_PER_WARP; r++) {
        const float4* crow = cbase + (size_t)r * D4;
        float4 c[8];
#pragma unroll
        for (int j = 0; j < 8; j++) c[j] = crow[lane + 32 * j];

        float dot = 0.0f;
#pragma unroll
        for (int j = 0; j < 8; j++)
            dot += c[j].x * hr[j].x + c[j].y * hr[j].y
                 + c[j].z * hr[j].z + c[j].w * hr[j].w;
#pragma unroll
        for (int off = 16; off; off >>= 1)
            dot += __shfl_xor_sync(0xffffffffu, dot, off);

        const int mk = mrow[r];
        const float logit = mk ? dot : -1.0e30f;
        if (lane == 0) g_logits[b * SS + s0 + r] = logit;

        // branchless online-softmax update
        const float m_new = fmaxf(m, logit);
        const float alpha = __expf(m - m_new);
        const float w     = mk ? __expf(dot - m_new) : 0.0f;
        l = l * alpha + w;
#pragma unroll
        for (int j = 0; j < 8; j++) {
            wc[j].x = wc[j].x * alpha + w * c[j].x;
            wc[j].y = wc[j].y * alpha + w * c[j].y;
            wc[j].z = wc[j].z * alpha + w * c[j].z;
            wc[j].w = wc[j].w * alpha + w * c[j].w;
        }
        m = m_new;
    }

    if (lane == 0) {
        g_m[b * PP + p] = m;
        g_l[b * PP + p] = l;
    }
    float4* dst = g_wc + ((size_t)b * PP + p) * D4;
#pragma unroll
    for (int j = 0; j < 8; j++) dst[lane + 32 * j] = wc[j];
}

// ---------------------------------------------------------------------------
// Pass 2: combine 128 partials per batch, write outputs.
// d_out layout: weighted_context [32,1024] then attn [32,2048].
// grid = BB, block = 256.
// ---------------------------------------------------------------------------
__global__ __launch_bounds__(256)
void attn_pass2(float* __restrict__ out)
{
    const int b = blockIdx.x;
    const int t = threadIdx.x;

    __shared__ float s_alpha[PP];
    __shared__ float sred[256];

    const float mv = (t < PP) ? g_m[b * PP + t] : -3.0e38f;

    // block max
    sred[t] = mv;
    __syncthreads();
    for (int st = 128; st; st >>= 1) {
        if (t < st) sred[t] = fmaxf(sred[t], sred[t + st]);
        __syncthreads();
    }
    const float m_g = sred[0];
    __syncthreads();

    const float alpha = (t < PP) ? __expf(mv - m_g) : 0.0f;
    if (t < PP) s_alpha[t] = alpha;
    const float lw = (t < PP) ? g_l[b * PP + t] * alpha : 0.0f;

    sred[t] = lw;
    __syncthreads();
    for (int st = 128; st; st >>= 1) {
        if (t < st) sred[t] += sred[t + st];
        __syncthreads();
    }
    const float invL = 1.0f / sred[0];
    __syncthreads();   // s_alpha fully visible (written before the sum barriers)

    // weighted_context: thread t owns float4 index t (d = 4t..4t+3)
    const float4* src = g_wc + (size_t)b * PP * D4 + t;
    float4 acc = make_float4(0.f, 0.f, 0.f, 0.f);
#pragma unroll 4
    for (int pp = 0; pp < PP; pp++) {
        const float a = s_alpha[pp];
        const float4 v = src[(size_t)pp * D4];
        acc.x += a * v.x;
        acc.y += a * v.y;
        acc.z += a * v.z;
        acc.w += a * v.w;
    }
    acc.x *= invL; acc.y *= invL; acc.z *= invL; acc.w *= invL;
    reinterpret_cast<float4*>(out)[b * D4 + t] = acc;

    // attn output
    float* out_attn = out + BB * DD;
    for (int s = t; s < SS; s += 256) {
        out_attn[b * SS + s] = __expf(g_logits[b * SS + s] - m_g) * invL;
    }
}

// ---------------------------------------------------------------------------
extern "C" void kernel_launch(void* const* d_in, const int* in_sizes, int n_in,
                              void* d_out, int out_size)
{
    const float* h    = (const float*)d_in[0];
    const float* ctx  = (const float*)d_in[1];
    const int*   mask = (const int*)d_in[2];
    float*       out  = (float*)d_out;

    attn_pass1<<<dim3(NCHUNK, BB), 256>>>(h, ctx, mask);
    attn_pass2<<<BB, 256>>>(out);
}

// round 3
// speedup vs baseline: 2.1899x; 2.1899x over previous
#include <cuda_runtime.h>
#include <cuda_bf16.h>
#include <cstddef>

// Problem dims (fixed by the reference setup_inputs)
#define BB 32
#define SS 2048
#define DD 1024
#define D4 (DD / 4)            // 256 float4 per row
#define ROWS_PER_WARP 32
#define WARPS 8
#define PP (SS / ROWS_PER_WARP)   // 64 partials per batch
#define NCHUNK (PP / WARPS)       // 8 CTAs per batch

// Scratch (allocation-free rule: __device__ globals)
__device__ float  g_logits[BB * SS];            // 256 KB, masked logits
__device__ float  g_m[BB * PP];
__device__ float  g_l[BB * PP];
__device__ float4 g_wc[(size_t)BB * PP * D4];   // 8 MB partial weighted sums

// ---------------------------------------------------------------------------
// Pass 1: single streaming pass over context with online softmax.
// Masked rows (mask==0) are NOT read from DRAM at all (they contribute 0).
// grid = (NCHUNK, BB), block = 256 (8 warps). Each warp: 32 consecutive rows.
// ---------------------------------------------------------------------------
__global__ __launch_bounds__(256, 2)
void attn_pass1(const float* __restrict__ h,
                const float* __restrict__ ctx,
                const int* __restrict__ mask)
{
    const int b     = blockIdx.y;
    const int chunk = blockIdx.x;
    const int warp  = threadIdx.x >> 5;
    const int lane  = threadIdx.x & 31;
    const int p     = chunk * WARPS + warp;     // partial index in [0,PP)
    const int s0    = p * ROWS_PER_WARP;        // first row of this warp

    // h row -> registers (reused for every context row)
    const float4* h4 = reinterpret_cast<const float4*>(h) + b * D4;
    float4 hr[8];
#pragma unroll
    for (int j = 0; j < 8; j++) hr[j] = h4[lane + 32 * j];

    // one coalesced load of this warp's 32 mask values
    const int mv = mask[b * SS + s0 + lane];

    float m = -3.0e38f;   // running max (finite sentinel)
    float l = 0.0f;       // running sum of exp
    float4 wc[8];
#pragma unroll
    for (int j = 0; j < 8; j++) wc[j] = make_float4(0.f, 0.f, 0.f, 0.f);

    const float4* cbase = reinterpret_cast<const float4*>(ctx)
                          + ((size_t)b * SS + s0) * D4;
    float* lrow = g_logits + b * SS + s0;

#pragma unroll 1
    for (int r = 0; r < ROWS_PER_WARP; r++) {
        const int mk = __shfl_sync(0xffffffffu, mv, r);   // warp-uniform
        if (!mk) {
            if (lane == 0) lrow[r] = -1.0e30f;
            continue;                                     // skip the 4KB read
        }

        const float4* crow = cbase + (size_t)r * D4;
        float4 c[8];
#pragma unroll
        for (int j = 0; j < 8; j++) c[j] = crow[lane + 32 * j];

        float dot = 0.0f;
#pragma unroll
        for (int j = 0; j < 8; j++)
            dot += c[j].x * hr[j].x + c[j].y * hr[j].y
                 + c[j].z * hr[j].z + c[j].w * hr[j].w;
#pragma unroll
        for (int off = 16; off; off >>= 1)
            dot += __shfl_xor_sync(0xffffffffu, dot, off);

        if (lane == 0) lrow[r] = dot;

        // deferred rescale: only when a new max appears (warp-uniform branch)
        if (dot > m) {
            const float alpha = __expf(m - dot);
            l *= alpha;
#pragma unroll
            for (int j = 0; j < 8; j++) {
                wc[j].x *= alpha; wc[j].y *= alpha;
                wc[j].z *= alpha; wc[j].w *= alpha;
            }
            m = dot;
        }
        const float w = __expf(dot - m);
        l += w;
#pragma unroll
        for (int j = 0; j < 8; j++) {
            wc[j].x += w * c[j].x;
            wc[j].y += w * c[j].y;
            wc[j].z += w * c[j].z;
            wc[j].w += w * c[j].w;
        }
    }

    if (lane == 0) {
        g_m[b * PP + p] = m;
        g_l[b * PP + p] = l;
    }
    float4* dst = g_wc + ((size_t)b * PP + p) * D4;
#pragma unroll
    for (int j = 0; j < 8; j++) dst[lane + 32 * j] = wc[j];
}

// ---------------------------------------------------------------------------
// Pass 2: combine PP partials per batch, write outputs.
// d_out layout: weighted_context [32,1024] then attn [32,2048].
// grid = (BB, 12): parts 0..7 -> 32-float4 slices of weighted_context,
//                  parts 8..11 -> 512-element slices of attn.
// Each block redundantly recomputes the (cheap) global m / L stats.
// ---------------------------------------------------------------------------
__global__ __launch_bounds__(256)
void attn_pass2(float* __restrict__ out)
{
    const int b    = blockIdx.x;
    const int part = blockIdx.y;
    const int t    = threadIdx.x;
    const int w    = t >> 5;
    const int lane = t & 31;

    __shared__ float sm[PP], sl[PP];
    __shared__ float s_stats[2];
    if (t < PP) { sm[t] = g_m[b * PP + t]; sl[t] = g_l[b * PP + t]; }
    __syncthreads();

    if (t < 32) {
        float mv = fmaxf(sm[t], sm[t + 32]);
#pragma unroll
        for (int off = 16; off; off >>= 1)
            mv = fmaxf(mv, __shfl_xor_sync(0xffffffffu, mv, off));
        float lw = sl[t] * __expf(sm[t] - mv)
                 + sl[t + 32] * __expf(sm[t + 32] - mv);
#pragma unroll
        for (int off = 16; off; off >>= 1)
            lw += __shfl_xor_sync(0xffffffffu, lw, off);
        if (t == 0) { s_stats[0] = mv; s_stats[1] = 1.0f / lw; }
    }
    __syncthreads();
    const float m_g  = s_stats[0];
    const float invL = s_stats[1];

    if (part < 8) {
        // weighted_context slice: float4 columns [part*32, part*32+32)
        // warp w accumulates partials p = w, w+8, ..., w+56
        const float4* base = g_wc + (size_t)b * PP * D4 + part * 32 + lane;
        float4 acc = make_float4(0.f, 0.f, 0.f, 0.f);
#pragma unroll
        for (int i = 0; i < 8; i++) {
            const int p = w + 8 * i;
            const float a = __expf(sm[p] - m_g);
            const float4 v = base[(size_t)p * D4];
            acc.x += a * v.x; acc.y += a * v.y;
            acc.z += a * v.z; acc.w += a * v.w;
        }
        __shared__ float4 sacc[8][32];
        sacc[w][lane] = acc;
        __syncthreads();
        if (w == 0) {
#pragma unroll
            for (int r = 1; r < 8; r++) {
                const float4 v = sacc[r][lane];
                acc.x += v.x; acc.y += v.y; acc.z += v.z; acc.w += v.w;
            }
            acc.x *= invL; acc.y *= invL; acc.z *= invL; acc.w *= invL;
            reinterpret_cast<float4*>(out)[b * D4 + part * 32 + lane] = acc;
        }
    } else {
        // attn slice: 512 s-values, 2 per thread (float2)
        const int s0 = (part - 8) * 512;
        const float2* lg = reinterpret_cast<const float2*>(g_logits + b * SS + s0);
        float2* oa = reinterpret_cast<float2*>(out + BB * DD + b * SS + s0);
        const float2 v = lg[t];
        float2 o;
        o.x = __expf(v.x - m_g) * invL;
        o.y = __expf(v.y - m_g) * invL;
        oa[t] = o;
    }
}

// ---------------------------------------------------------------------------
extern "C" void kernel_launch(void* const* d_in, const int* in_sizes, int n_in,
                              void* d_out, int out_size)
{
    const float* h    = (const float*)d_in[0];
    const float* ctx  = (const float*)d_in[1];
    const int*   mask = (const int*)d_in[2];
    float*       out  = (float*)d_out;

    attn_pass1<<<dim3(NCHUNK, BB), 256>>>(h, ctx, mask);
    attn_pass2<<<dim3(BB, 12), 256>>>(out);
}